// round 5
// baseline (speedup 1.0000x reference)
#include <cuda_runtime.h>
#include <cstdint>
#include <cstddef>

// Problem constants
#define OSIZE 224
#define NB 64
#define HM 512
#define WMETA 513
#define WMC 512          // image width without metadata column
#define SPITCH 520       // smem row pitch (floats)

// Per-batch crop params
__device__ int g_pi[NB], g_pj[NB], g_ph[NB], g_pw[NB], g_pflip[NB];

// ---------------------------------------------------------------------------
// Threefry-2x32 (JAX-compatible): 20 rounds, key schedule ks2 = k0^k1^parity
// ---------------------------------------------------------------------------
__device__ __forceinline__ void tf2x32(uint32_t k0, uint32_t k1,
                                       uint32_t x0, uint32_t x1,
                                       uint32_t &o0, uint32_t &o1) {
    uint32_t ks2 = k0 ^ k1 ^ 0x1BD11BDAu;
    x0 += k0; x1 += k1;
#define TF_RND(r) { x0 += x1; x1 = (x1 << (r)) | (x1 >> (32 - (r))); x1 ^= x0; }
    TF_RND(13) TF_RND(15) TF_RND(26) TF_RND(6)
    x0 += k1;  x1 += ks2 + 1u;
    TF_RND(17) TF_RND(29) TF_RND(16) TF_RND(24)
    x0 += ks2; x1 += k0 + 2u;
    TF_RND(13) TF_RND(15) TF_RND(26) TF_RND(6)
    x0 += k0;  x1 += k1 + 3u;
    TF_RND(17) TF_RND(29) TF_RND(16) TF_RND(24)
    x0 += k1;  x1 += ks2 + 4u;
    TF_RND(13) TF_RND(15) TF_RND(26) TF_RND(6)
    x0 += ks2; x1 += k0 + 5u;
#undef TF_RND
    o0 = x0; o1 = x1;
}

// Partitionable (foldlike) JAX derivations:
//   split(key, n)[i]            = (o0, o1) of threefry(key, (0, i))
//   fold_in(key, t)             = (o0, o1) of threefry(key, (0, t))
//   random_bits(key,32,(N,))[b] = o0 ^ o1 of threefry(key, (0, b))
__device__ __forceinline__ uint32_t rbits_part(uint32_t k0, uint32_t k1, int idx) {
    uint32_t o0, o1;
    tf2x32(k0, k1, 0u, (uint32_t)idx, o0, o1);
    return o0 ^ o1;
}

// bits -> [0,1) float, JAX style: (bits>>9 | 0x3f800000) as float - 1
__device__ __forceinline__ float bits_to_unit(uint32_t bits) {
    return __uint_as_float((bits >> 9) | 0x3F800000u) - 1.0f;
}

// ---------------------------------------------------------------------------
// Kernel 1: params, 64 blocks x 32 threads. Lanes 0..9 = tries (parallel),
// lane 10 = flip draw; ballot picks the FIRST valid try (matches ~success).
// Param-path float math uses _rn intrinsics (IEEE RN regardless of flags).
// ---------------------------------------------------------------------------
__global__ void params_kernel(const float* __restrict__ x) {
    const int b = blockIdx.x;
    const int lane = threadIdx.x;
    const unsigned FULL = 0xFFFFFFFFu;

    // root key(42) = (0,42); split -> kflip=tf(key,(0,0)), kparams=tf(key,(0,1))
    uint32_t kf0, kf1, kp0, kp1;
    tf2x32(0u, 42u, 0u, 0u, kf0, kf1);
    tf2x32(0u, 42u, 0u, 1u, kp0, kp1);

    const size_t img_stride = (size_t)3 * HM * WMETA;
    float Hf = __ldg(x + (size_t)b * img_stride + 512);
    float Wf = __ldg(x + (size_t)b * img_stride + (size_t)HM * WMETA + 512);

    const float lg_lo = -0.22314355131420976f;  // float32(log(0.8))
    const float lg_hi =  0.22314355131420976f;  // float32(log(1.25))

    int   flip = 0;
    bool  valid = false;
    float ch = 0.f, cw = 0.f, ri = 0.f, rj = 0.f;

    if (lane < 10) {
        uint32_t kt0, kt1;
        tf2x32(kp0, kp1, 0u, (uint32_t)lane, kt0, kt1);
        uint32_t ka0, ka1, kb0, kb1, kc0, kc1, kd0, kd1;
        tf2x32(kt0, kt1, 0u, 0u, ka0, ka1);  // target_area
        tf2x32(kt0, kt1, 0u, 1u, kb0, kb1);  // aspect
        tf2x32(kt0, kt1, 0u, 2u, kc0, kc1);  // rand_i
        tf2x32(kt0, kt1, 0u, 3u, kd0, kd1);  // rand_j

        float u1 = bits_to_unit(rbits_part(ka0, ka1, b));
        u1 = fmaxf(0.1f, __fadd_rn(__fmul_rn(u1, 1.0f - 0.1f), 0.1f));
        float u2 = bits_to_unit(rbits_part(kb0, kb1, b));
        u2 = fmaxf(lg_lo, __fadd_rn(__fmul_rn(u2, lg_hi - lg_lo), lg_lo));

        float area = __fmul_rn(Hf, Wf);
        float ta = __fmul_rn(area, u1);
        float aspect = expf(u2);   // libdevice __nv_expf
        cw = rintf(__fsqrt_rn(__fmul_rn(ta, aspect)));
        ch = rintf(__fsqrt_rn(__fdiv_rn(ta, aspect)));

        valid = (cw > 0.0f) && (cw <= Wf) && (ch > 0.0f) && (ch <= Hf);

        float max_i = fmaxf(__fadd_rn(__fsub_rn(Hf, ch), 1.0f), 1.0f);
        float max_j = fmaxf(__fadd_rn(__fsub_rn(Wf, cw), 1.0f), 1.0f);
        float u3 = bits_to_unit(rbits_part(kc0, kc1, b));
        float u4 = bits_to_unit(rbits_part(kd0, kd1, b));
        ri = floorf(__fmul_rn(u3, max_i));
        rj = floorf(__fmul_rn(u4, max_j));
    } else if (lane == 10) {
        flip = bits_to_unit(rbits_part(kf0, kf1, b)) > 0.5f;
    }

    unsigned vmask = __ballot_sync(FULL, valid) & 0x3FFu;
    int src = vmask ? (__ffs(vmask) - 1) : -1;

    float fh, fw, fi, fj;
    if (src >= 0) {
        fh = __shfl_sync(FULL, ch, src);
        fw = __shfl_sync(FULL, cw, src);
        fi = __shfl_sync(FULL, ri, src);
        fj = __shfl_sync(FULL, rj, src);
    } else {
        float in_ratio = __fdiv_rn(Wf, Hf);
        fw = (in_ratio > 1.25f) ? rintf(__fmul_rn(Hf, 1.25f)) : Wf;
        fh = (in_ratio < 0.8f)  ? rintf(__fdiv_rn(Wf, 0.8f))  : Hf;
        fi = floorf(__fdiv_rn(__fsub_rn(Hf, fh), 2.0f));
        fj = floorf(__fdiv_rn(__fsub_rn(Wf, fw), 2.0f));
    }
    int flipv = __shfl_sync(FULL, flip, 10);

    if (lane == 0) {
        g_pi[b] = (int)fi; g_pj[b] = (int)fj;
        g_ph[b] = (int)fh; g_pw[b] = (int)fw;
        g_pflip[b] = flipv;
    }
}

// ---------------------------------------------------------------------------
// Kernel 2: flip + crop + bilinear resize via smem row staging.
// One block per (b, oy). y0/y1 are block-uniform; the x-taps span one
// contiguous orig-column range [xbeg, xbeg+cw). Stage 6 row segments
// (3 ch x 2 rows) with coalesced loads, then do the 12 taps from smem.
// ---------------------------------------------------------------------------
__global__ void __launch_bounds__(OSIZE)
resize_kernel(const float* __restrict__ x, float* __restrict__ out) {
    __shared__ float s[6][SPITCH];

    const int tid = threadIdx.x;  // ox
    const int oy = blockIdx.x;    // 0..223
    const int b  = blockIdx.y;    // 0..63

    const int ci = g_pi[b], cj = g_pj[b], ch = g_ph[b], cw = g_pw[b];
    const int flip = g_pflip[b];
    const float hf = (float)ch, wf = (float)cw;

    // y mapping (block-uniform), IEEE ops so floor boundaries match XLA
    float ysv = __fsub_rn(__fdiv_rn(__fmul_rn((float)oy + 0.5f, hf), 224.0f), 0.5f);
    ysv = fminf(fmaxf(ysv, 0.0f), hf - 1.0f);
    float y0f = floorf(ysv);
    float wy = ysv - y0f;
    int y0 = min(max((int)y0f + ci, 0), HM - 1);
    int ytop = min(max(ci + ch - 1, 0), HM - 1);
    int y1 = min(max(y0 + 1, 0), ytop);

    // Staged orig-column range: taps fall in [cj, cj+cw-1] unflipped,
    // or [513-cj-cw, 512-cj] flipped. Length = cw.
    const int xbeg = flip ? (513 - cj - cw) : cj;
    const int lenx = cw;

    const float* base = x + (size_t)b * 3 * HM * WMETA;

    // Stage 6 row segments, coalesced
#pragma unroll
    for (int seg = 0; seg < 6; seg++) {
        const int c = seg >> 1;
        const int yy = (seg & 1) ? y1 : y0;
        const float* row = base + ((size_t)c * HM + yy) * WMETA + xbeg;
        for (int xo = tid; xo < lenx; xo += OSIZE)
            s[seg][xo] = __ldg(row + xo);
    }
    __syncthreads();

    // x mapping (per thread)
    const int ox = tid;
    float xsv = __fsub_rn(__fdiv_rn(__fmul_rn((float)ox + 0.5f, wf), 224.0f), 0.5f);
    xsv = fminf(fmaxf(xsv, 0.0f), wf - 1.0f);
    float x0f = floorf(xsv);
    float wx = xsv - x0f;
    int x0 = min(max((int)x0f + cj, 0), WMC - 1);
    int xtop = min(max(cj + cw - 1, 0), WMC - 1);
    int x1 = min(max(x0 + 1, 0), xtop);
    if (flip) { x0 = WMC - x0; x1 = WMC - x1; }

    const int i0 = x0 - xbeg;
    const int i1 = x1 - xbeg;
    const float omwx = 1.0f - wx, omwy = 1.0f - wy;

#pragma unroll
    for (int c = 0; c < 3; c++) {
        float g00 = s[c * 2 + 0][i0];
        float g01 = s[c * 2 + 0][i1];
        float g10 = s[c * 2 + 1][i0];
        float g11 = s[c * 2 + 1][i1];
        float top = omwx * g00 + wx * g01;
        float bot = omwx * g10 + wx * g11;
        out[(((size_t)b * 3 + c) * OSIZE + oy) * OSIZE + ox] = omwy * top + wy * bot;
    }
}

extern "C" void kernel_launch(void* const* d_in, const int* in_sizes, int n_in,
                              void* d_out, int out_size) {
    const float* x = (const float*)d_in[0];
    float* out = (float*)d_out;

    params_kernel<<<NB, 32>>>(x);
    dim3 grid(OSIZE, NB);
    resize_kernel<<<grid, OSIZE>>>(x, out);
}

// round 6
// speedup vs baseline: 2.0233x; 2.0233x over previous
#include <cuda_runtime.h>
#include <cstdint>
#include <cstddef>

// Problem constants
#define OSIZE 224
#define NB 64
#define HM 512
#define WMETA 513
#define WMC 512          // image width without metadata column

// Packed per-batch crop params: x=pi, y=pj, z=ph, w = pw | (flip<<16)
__device__ int4 g_prm[NB];

// ---------------------------------------------------------------------------
// Threefry-2x32 (JAX-compatible): 20 rounds, key schedule ks2 = k0^k1^parity
// ---------------------------------------------------------------------------
__device__ __forceinline__ void tf2x32(uint32_t k0, uint32_t k1,
                                       uint32_t x0, uint32_t x1,
                                       uint32_t &o0, uint32_t &o1) {
    uint32_t ks2 = k0 ^ k1 ^ 0x1BD11BDAu;
    x0 += k0; x1 += k1;
#define TF_RND(r) { x0 += x1; x1 = (x1 << (r)) | (x1 >> (32 - (r))); x1 ^= x0; }
    TF_RND(13) TF_RND(15) TF_RND(26) TF_RND(6)
    x0 += k1;  x1 += ks2 + 1u;
    TF_RND(17) TF_RND(29) TF_RND(16) TF_RND(24)
    x0 += ks2; x1 += k0 + 2u;
    TF_RND(13) TF_RND(15) TF_RND(26) TF_RND(6)
    x0 += k0;  x1 += k1 + 3u;
    TF_RND(17) TF_RND(29) TF_RND(16) TF_RND(24)
    x0 += k1;  x1 += ks2 + 4u;
    TF_RND(13) TF_RND(15) TF_RND(26) TF_RND(6)
    x0 += ks2; x1 += k0 + 5u;
#undef TF_RND
    o0 = x0; o1 = x1;
}

// Partitionable (foldlike) JAX derivations:
//   split(key, n)[i]            = (o0, o1) of threefry(key, (0, i))
//   fold_in(key, t)             = (o0, o1) of threefry(key, (0, t))
//   random_bits(key,32,(N,))[b] = o0 ^ o1 of threefry(key, (0, b))
__device__ __forceinline__ uint32_t rbits_part(uint32_t k0, uint32_t k1, int idx) {
    uint32_t o0, o1;
    tf2x32(k0, k1, 0u, (uint32_t)idx, o0, o1);
    return o0 ^ o1;
}

// bits -> [0,1) float, JAX style: (bits>>9 | 0x3f800000) as float - 1
__device__ __forceinline__ float bits_to_unit(uint32_t bits) {
    return __uint_as_float((bits >> 9) | 0x3F800000u) - 1.0f;
}

// ---------------------------------------------------------------------------
// Kernel 1: params, 64 blocks x 32 threads. Lanes 0..9 = tries (parallel),
// lane 10 = flip draw; ballot picks the FIRST valid try (matches ~success).
// Param-path float math uses _rn intrinsics (IEEE RN regardless of flags).
// ---------------------------------------------------------------------------
__global__ void params_kernel(const float* __restrict__ x) {
    const int b = blockIdx.x;
    const int lane = threadIdx.x;
    const unsigned FULL = 0xFFFFFFFFu;

    // root key(42) = (0,42); split -> kflip=tf(key,(0,0)), kparams=tf(key,(0,1))
    uint32_t kf0, kf1, kp0, kp1;
    tf2x32(0u, 42u, 0u, 0u, kf0, kf1);
    tf2x32(0u, 42u, 0u, 1u, kp0, kp1);

    const int img_stride = 3 * HM * WMETA;
    float Hf = __ldg(x + b * img_stride + 512);
    float Wf = __ldg(x + b * img_stride + HM * WMETA + 512);

    const float lg_lo = -0.22314355131420976f;  // float32(log(0.8))
    const float lg_hi =  0.22314355131420976f;  // float32(log(1.25))

    int   flip = 0;
    bool  valid = false;
    float ch = 0.f, cw = 0.f, ri = 0.f, rj = 0.f;

    if (lane < 10) {
        uint32_t kt0, kt1;
        tf2x32(kp0, kp1, 0u, (uint32_t)lane, kt0, kt1);
        uint32_t ka0, ka1, kb0, kb1, kc0, kc1, kd0, kd1;
        tf2x32(kt0, kt1, 0u, 0u, ka0, ka1);  // target_area
        tf2x32(kt0, kt1, 0u, 1u, kb0, kb1);  // aspect
        tf2x32(kt0, kt1, 0u, 2u, kc0, kc1);  // rand_i
        tf2x32(kt0, kt1, 0u, 3u, kd0, kd1);  // rand_j

        float u1 = bits_to_unit(rbits_part(ka0, ka1, b));
        u1 = fmaxf(0.1f, __fadd_rn(__fmul_rn(u1, 1.0f - 0.1f), 0.1f));
        float u2 = bits_to_unit(rbits_part(kb0, kb1, b));
        u2 = fmaxf(lg_lo, __fadd_rn(__fmul_rn(u2, lg_hi - lg_lo), lg_lo));

        float area = __fmul_rn(Hf, Wf);
        float ta = __fmul_rn(area, u1);
        float aspect = expf(u2);   // libdevice __nv_expf
        cw = rintf(__fsqrt_rn(__fmul_rn(ta, aspect)));
        ch = rintf(__fsqrt_rn(__fdiv_rn(ta, aspect)));

        valid = (cw > 0.0f) && (cw <= Wf) && (ch > 0.0f) && (ch <= Hf);

        float max_i = fmaxf(__fadd_rn(__fsub_rn(Hf, ch), 1.0f), 1.0f);
        float max_j = fmaxf(__fadd_rn(__fsub_rn(Wf, cw), 1.0f), 1.0f);
        float u3 = bits_to_unit(rbits_part(kc0, kc1, b));
        float u4 = bits_to_unit(rbits_part(kd0, kd1, b));
        ri = floorf(__fmul_rn(u3, max_i));
        rj = floorf(__fmul_rn(u4, max_j));
    } else if (lane == 10) {
        flip = bits_to_unit(rbits_part(kf0, kf1, b)) > 0.5f;
    }

    unsigned vmask = __ballot_sync(FULL, valid) & 0x3FFu;
    int src = vmask ? (__ffs(vmask) - 1) : -1;

    float fh, fw, fi, fj;
    if (src >= 0) {
        fh = __shfl_sync(FULL, ch, src);
        fw = __shfl_sync(FULL, cw, src);
        fi = __shfl_sync(FULL, ri, src);
        fj = __shfl_sync(FULL, rj, src);
    } else {
        float in_ratio = __fdiv_rn(Wf, Hf);
        fw = (in_ratio > 1.25f) ? rintf(__fmul_rn(Hf, 1.25f)) : Wf;
        fh = (in_ratio < 0.8f)  ? rintf(__fdiv_rn(Wf, 0.8f))  : Hf;
        fi = floorf(__fdiv_rn(__fsub_rn(Hf, fh), 2.0f));
        fj = floorf(__fdiv_rn(__fsub_rn(Wf, fw), 2.0f));
    }
    int flipv = __shfl_sync(FULL, flip, 10);

    if (lane == 0) {
        int4 p;
        p.x = (int)fi;
        p.y = (int)fj;
        p.z = (int)fh;
        p.w = (int)fw | (flipv << 16);
        g_prm[b] = p;
    }
}

// ---------------------------------------------------------------------------
// Kernel 2: flip + crop + bilinear resize (direct gather, 32-bit indexing).
// One block per (b, oy); 224 threads, one ox each, 3 channels.
// ---------------------------------------------------------------------------
__global__ void __launch_bounds__(OSIZE)
resize_kernel(const float* __restrict__ x, float* __restrict__ out) {
    const int ox = threadIdx.x;   // 0..223
    const int oy = blockIdx.x;    // 0..223
    const int b  = blockIdx.y;    // 0..63

    const int4 p = __ldg(&g_prm[b]);
    const int ci = p.x, cj = p.y, ch = p.z;
    const int cw = p.w & 0xFFFF;
    const int flip = p.w >> 16;
    const float hf = (float)ch, wf = (float)cw;

    // y mapping (align_corners=False), IEEE ops so floor boundaries match XLA
    float ysv = __fsub_rn(__fdiv_rn(__fmul_rn((float)oy + 0.5f, hf), 224.0f), 0.5f);
    ysv = fminf(fmaxf(ysv, 0.0f), hf - 1.0f);
    float y0f = floorf(ysv);
    float wy = ysv - y0f;
    int y0 = min(max((int)y0f + ci, 0), HM - 1);
    int ytop = min(max(ci + ch - 1, 0), HM - 1);
    int y1 = min(max(y0 + 1, 0), ytop);

    // x mapping
    float xsv = __fsub_rn(__fdiv_rn(__fmul_rn((float)ox + 0.5f, wf), 224.0f), 0.5f);
    xsv = fminf(fmaxf(xsv, 0.0f), wf - 1.0f);
    float x0f = floorf(xsv);
    float wx = xsv - x0f;
    int x0 = min(max((int)x0f + cj, 0), WMC - 1);
    int xtop = min(max(cj + cw - 1, 0), WMC - 1);
    int x1 = min(max(x0 + 1, 0), xtop);

    // flip: x_no_meta (flipped)[xc] == orig[512 - xc]
    if (flip) { x0 = WMC - x0; x1 = WMC - x1; }

    const int base = b * (3 * HM * WMETA);
    const int r0 = base + y0 * WMETA;
    const int r1 = base + y1 * WMETA;
    const float omwx = 1.0f - wx, omwy = 1.0f - wy;

    int oidx = (b * 3 * OSIZE + oy) * OSIZE + ox;   // c stride = OSIZE*OSIZE

#pragma unroll
    for (int c = 0; c < 3; c++) {
        const int co = c * (HM * WMETA);
        float g00 = __ldg(x + r0 + co + x0);
        float g01 = __ldg(x + r0 + co + x1);
        float g10 = __ldg(x + r1 + co + x0);
        float g11 = __ldg(x + r1 + co + x1);
        float top = omwx * g00 + wx * g01;
        float bot = omwx * g10 + wx * g11;
        out[oidx + c * (OSIZE * OSIZE)] = omwy * top + wy * bot;
    }
}

extern "C" void kernel_launch(void* const* d_in, const int* in_sizes, int n_in,
                              void* d_out, int out_size) {
    const float* x = (const float*)d_in[0];
    float* out = (float*)d_out;

    params_kernel<<<NB, 32>>>(x);
    dim3 grid(OSIZE, NB);
    resize_kernel<<<grid, OSIZE>>>(x, out);
}

// round 7
// speedup vs baseline: 2.3817x; 1.1771x over previous
#include <cuda_runtime.h>
#include <cstdint>
#include <cstddef>

// Problem constants
#define OSIZE 224
#define NB 64
#define HM 512
#define WMETA 513
#define WMC 512          // image width without metadata column
#define ROWS_PER_BLK 2

// Packed per-batch crop params: x=pi, y=pj, z=ph, w = pw | (flip<<16)
__device__ int4 g_prm[NB];

// ---------------------------------------------------------------------------
// Threefry-2x32 (JAX-compatible): 20 rounds, key schedule ks2 = k0^k1^parity
// ---------------------------------------------------------------------------
__device__ __forceinline__ void tf2x32(uint32_t k0, uint32_t k1,
                                       uint32_t x0, uint32_t x1,
                                       uint32_t &o0, uint32_t &o1) {
    uint32_t ks2 = k0 ^ k1 ^ 0x1BD11BDAu;
    x0 += k0; x1 += k1;
#define TF_RND(r) { x0 += x1; x1 = (x1 << (r)) | (x1 >> (32 - (r))); x1 ^= x0; }
    TF_RND(13) TF_RND(15) TF_RND(26) TF_RND(6)
    x0 += k1;  x1 += ks2 + 1u;
    TF_RND(17) TF_RND(29) TF_RND(16) TF_RND(24)
    x0 += ks2; x1 += k0 + 2u;
    TF_RND(13) TF_RND(15) TF_RND(26) TF_RND(6)
    x0 += k0;  x1 += k1 + 3u;
    TF_RND(17) TF_RND(29) TF_RND(16) TF_RND(24)
    x0 += k1;  x1 += ks2 + 4u;
    TF_RND(13) TF_RND(15) TF_RND(26) TF_RND(6)
    x0 += ks2; x1 += k0 + 5u;
#undef TF_RND
    o0 = x0; o1 = x1;
}

// Partitionable (foldlike) JAX derivations:
//   split(key, n)[i]            = (o0, o1) of threefry(key, (0, i))
//   fold_in(key, t)             = (o0, o1) of threefry(key, (0, t))
//   random_bits(key,32,(N,))[b] = o0 ^ o1 of threefry(key, (0, b))
__device__ __forceinline__ uint32_t rbits_part(uint32_t k0, uint32_t k1, int idx) {
    uint32_t o0, o1;
    tf2x32(k0, k1, 0u, (uint32_t)idx, o0, o1);
    return o0 ^ o1;
}

// bits -> [0,1) float, JAX style: (bits>>9 | 0x3f800000) as float - 1
__device__ __forceinline__ float bits_to_unit(uint32_t bits) {
    return __uint_as_float((bits >> 9) | 0x3F800000u) - 1.0f;
}

// ---------------------------------------------------------------------------
// Kernel 1: params, 64 blocks x 32 threads. Lanes 0..9 = tries (parallel),
// lane 10 = flip draw; ballot picks the FIRST valid try (matches ~success).
// Param-path float math uses _rn intrinsics (IEEE RN regardless of flags).
// ---------------------------------------------------------------------------
__global__ void params_kernel(const float* __restrict__ x) {
    const int b = blockIdx.x;
    const int lane = threadIdx.x;
    const unsigned FULL = 0xFFFFFFFFu;

    // root key(42) = (0,42); split -> kflip=tf(key,(0,0)), kparams=tf(key,(0,1))
    uint32_t kf0, kf1, kp0, kp1;
    tf2x32(0u, 42u, 0u, 0u, kf0, kf1);
    tf2x32(0u, 42u, 0u, 1u, kp0, kp1);

    const int img_stride = 3 * HM * WMETA;
    float Hf = __ldg(x + b * img_stride + 512);
    float Wf = __ldg(x + b * img_stride + HM * WMETA + 512);

    const float lg_lo = -0.22314355131420976f;  // float32(log(0.8))
    const float lg_hi =  0.22314355131420976f;  // float32(log(1.25))

    int   flip = 0;
    bool  valid = false;
    float ch = 0.f, cw = 0.f, ri = 0.f, rj = 0.f;

    if (lane < 10) {
        uint32_t kt0, kt1;
        tf2x32(kp0, kp1, 0u, (uint32_t)lane, kt0, kt1);
        uint32_t ka0, ka1, kb0, kb1, kc0, kc1, kd0, kd1;
        tf2x32(kt0, kt1, 0u, 0u, ka0, ka1);  // target_area
        tf2x32(kt0, kt1, 0u, 1u, kb0, kb1);  // aspect
        tf2x32(kt0, kt1, 0u, 2u, kc0, kc1);  // rand_i
        tf2x32(kt0, kt1, 0u, 3u, kd0, kd1);  // rand_j

        float u1 = bits_to_unit(rbits_part(ka0, ka1, b));
        u1 = fmaxf(0.1f, __fadd_rn(__fmul_rn(u1, 1.0f - 0.1f), 0.1f));
        float u2 = bits_to_unit(rbits_part(kb0, kb1, b));
        u2 = fmaxf(lg_lo, __fadd_rn(__fmul_rn(u2, lg_hi - lg_lo), lg_lo));

        float area = __fmul_rn(Hf, Wf);
        float ta = __fmul_rn(area, u1);
        float aspect = expf(u2);   // libdevice __nv_expf
        cw = rintf(__fsqrt_rn(__fmul_rn(ta, aspect)));
        ch = rintf(__fsqrt_rn(__fdiv_rn(ta, aspect)));

        valid = (cw > 0.0f) && (cw <= Wf) && (ch > 0.0f) && (ch <= Hf);

        float max_i = fmaxf(__fadd_rn(__fsub_rn(Hf, ch), 1.0f), 1.0f);
        float max_j = fmaxf(__fadd_rn(__fsub_rn(Wf, cw), 1.0f), 1.0f);
        float u3 = bits_to_unit(rbits_part(kc0, kc1, b));
        float u4 = bits_to_unit(rbits_part(kd0, kd1, b));
        ri = floorf(__fmul_rn(u3, max_i));
        rj = floorf(__fmul_rn(u4, max_j));
    } else if (lane == 10) {
        flip = bits_to_unit(rbits_part(kf0, kf1, b)) > 0.5f;
    }

    unsigned vmask = __ballot_sync(FULL, valid) & 0x3FFu;
    int src = vmask ? (__ffs(vmask) - 1) : -1;

    float fh, fw, fi, fj;
    if (src >= 0) {
        fh = __shfl_sync(FULL, ch, src);
        fw = __shfl_sync(FULL, cw, src);
        fi = __shfl_sync(FULL, ri, src);
        fj = __shfl_sync(FULL, rj, src);
    } else {
        float in_ratio = __fdiv_rn(Wf, Hf);
        fw = (in_ratio > 1.25f) ? rintf(__fmul_rn(Hf, 1.25f)) : Wf;
        fh = (in_ratio < 0.8f)  ? rintf(__fdiv_rn(Wf, 0.8f))  : Hf;
        fi = floorf(__fdiv_rn(__fsub_rn(Hf, fh), 2.0f));
        fj = floorf(__fdiv_rn(__fsub_rn(Wf, fw), 2.0f));
    }
    int flipv = __shfl_sync(FULL, flip, 10);

    if (lane == 0) {
        int4 p;
        p.x = (int)fi;
        p.y = (int)fj;
        p.z = (int)fh;
        p.w = (int)fw | (flipv << 16);
        g_prm[b] = p;
    }
}

// ---------------------------------------------------------------------------
// Kernel 2: flip + crop + bilinear resize (direct gather, 32-bit indexing).
// One block per (b, oy-pair); 224 threads. Each thread: 1 ox, 2 oy rows,
// 3 channels = 24 front-batched gathers (x-mapping shared across rows).
// ---------------------------------------------------------------------------
__global__ void __launch_bounds__(OSIZE)
resize_kernel(const float* __restrict__ x, float* __restrict__ out) {
    const int ox  = threadIdx.x;              // 0..223
    const int oy0 = blockIdx.x * ROWS_PER_BLK; // 0,2,..,222
    const int b   = blockIdx.y;               // 0..63

    const int4 p = __ldg(&g_prm[b]);
    const int ci = p.x, cj = p.y, ch = p.z;
    const int cw = p.w & 0xFFFF;
    const int flip = p.w >> 16;
    const float hf = (float)ch, wf = (float)cw;

    // x mapping (shared by both rows), IEEE ops so floors match XLA
    float xsv = __fsub_rn(__fdiv_rn(__fmul_rn((float)ox + 0.5f, wf), 224.0f), 0.5f);
    xsv = fminf(fmaxf(xsv, 0.0f), wf - 1.0f);
    float x0f = floorf(xsv);
    float wx = xsv - x0f;
    int x0 = min(max((int)x0f + cj, 0), WMC - 1);
    int xtop = min(max(cj + cw - 1, 0), WMC - 1);
    int x1 = min(max(x0 + 1, 0), xtop);
    if (flip) { x0 = WMC - x0; x1 = WMC - x1; }

    // y mappings for the two rows
    const int ytop = min(max(ci + ch - 1, 0), HM - 1);
    int y0r[ROWS_PER_BLK], y1r[ROWS_PER_BLK];
    float wyr[ROWS_PER_BLK];
#pragma unroll
    for (int r = 0; r < ROWS_PER_BLK; r++) {
        float ysv = __fsub_rn(__fdiv_rn(__fmul_rn((float)(oy0 + r) + 0.5f, hf), 224.0f), 0.5f);
        ysv = fminf(fmaxf(ysv, 0.0f), hf - 1.0f);
        float y0f = floorf(ysv);
        wyr[r] = ysv - y0f;
        int y0 = min(max((int)y0f + ci, 0), HM - 1);
        y0r[r] = y0;
        y1r[r] = min(max(y0 + 1, 0), ytop);
    }

    const int base = b * (3 * HM * WMETA);

    // Front-batched gathers: 2 rows x 3 channels x 4 taps = 24 independent LDGs
    float g00[ROWS_PER_BLK][3], g01[ROWS_PER_BLK][3];
    float g10[ROWS_PER_BLK][3], g11[ROWS_PER_BLK][3];
#pragma unroll
    for (int r = 0; r < ROWS_PER_BLK; r++) {
        const int r0 = base + y0r[r] * WMETA;
        const int r1 = base + y1r[r] * WMETA;
#pragma unroll
        for (int c = 0; c < 3; c++) {
            const int co = c * (HM * WMETA);
            g00[r][c] = __ldg(x + r0 + co + x0);
            g01[r][c] = __ldg(x + r0 + co + x1);
            g10[r][c] = __ldg(x + r1 + co + x0);
            g11[r][c] = __ldg(x + r1 + co + x1);
        }
    }

    const float omwx = 1.0f - wx;
    const int obase = (b * 3 * OSIZE + oy0) * OSIZE + ox;  // row stride OSIZE

#pragma unroll
    for (int r = 0; r < ROWS_PER_BLK; r++) {
        const float wy = wyr[r], omwy = 1.0f - wy;
#pragma unroll
        for (int c = 0; c < 3; c++) {
            float top = omwx * g00[r][c] + wx * g01[r][c];
            float bot = omwx * g10[r][c] + wx * g11[r][c];
            out[obase + c * (OSIZE * OSIZE) + r * OSIZE] = omwy * top + wy * bot;
        }
    }
}

extern "C" void kernel_launch(void* const* d_in, const int* in_sizes, int n_in,
                              void* d_out, int out_size) {
    const float* x = (const float*)d_in[0];
    float* out = (float*)d_out;

    params_kernel<<<NB, 32>>>(x);
    dim3 grid(OSIZE / ROWS_PER_BLK, NB);
    resize_kernel<<<grid, OSIZE>>>(x, out);
}

// round 8
// speedup vs baseline: 2.3853x; 1.0015x over previous
#include <cuda_runtime.h>
#include <cstdint>
#include <cstddef>

// Problem constants
#define OSIZE 224
#define NB 64
#define HM 512
#define WMETA 513
#define WMC 512          // image width without metadata column
#define ROWS_PER_BLK 4

// Packed per-batch crop params: x=pi, y=pj, z=ph, w = pw | (flip<<16)
__device__ int4 g_prm[NB];

// ---------------------------------------------------------------------------
// Threefry-2x32 (JAX-compatible): 20 rounds, key schedule ks2 = k0^k1^parity
// ---------------------------------------------------------------------------
__device__ __forceinline__ void tf2x32(uint32_t k0, uint32_t k1,
                                       uint32_t x0, uint32_t x1,
                                       uint32_t &o0, uint32_t &o1) {
    uint32_t ks2 = k0 ^ k1 ^ 0x1BD11BDAu;
    x0 += k0; x1 += k1;
#define TF_RND(r) { x0 += x1; x1 = (x1 << (r)) | (x1 >> (32 - (r))); x1 ^= x0; }
    TF_RND(13) TF_RND(15) TF_RND(26) TF_RND(6)
    x0 += k1;  x1 += ks2 + 1u;
    TF_RND(17) TF_RND(29) TF_RND(16) TF_RND(24)
    x0 += ks2; x1 += k0 + 2u;
    TF_RND(13) TF_RND(15) TF_RND(26) TF_RND(6)
    x0 += k0;  x1 += k1 + 3u;
    TF_RND(17) TF_RND(29) TF_RND(16) TF_RND(24)
    x0 += k1;  x1 += ks2 + 4u;
    TF_RND(13) TF_RND(15) TF_RND(26) TF_RND(6)
    x0 += ks2; x1 += k0 + 5u;
#undef TF_RND
    o0 = x0; o1 = x1;
}

// Partitionable (foldlike) JAX derivations:
//   split(key, n)[i]            = (o0, o1) of threefry(key, (0, i))
//   fold_in(key, t)             = (o0, o1) of threefry(key, (0, t))
//   random_bits(key,32,(N,))[b] = o0 ^ o1 of threefry(key, (0, b))
__device__ __forceinline__ uint32_t rbits_part(uint32_t k0, uint32_t k1, int idx) {
    uint32_t o0, o1;
    tf2x32(k0, k1, 0u, (uint32_t)idx, o0, o1);
    return o0 ^ o1;
}

// bits -> [0,1) float, JAX style: (bits>>9 | 0x3f800000) as float - 1
__device__ __forceinline__ float bits_to_unit(uint32_t bits) {
    return __uint_as_float((bits >> 9) | 0x3F800000u) - 1.0f;
}

// ---------------------------------------------------------------------------
// Kernel 1: params, 64 blocks x 32 threads. Lanes 0..9 = tries (parallel),
// lane 10 = flip draw; ballot picks the FIRST valid try (matches ~success).
// Param-path float math uses _rn intrinsics (IEEE RN regardless of flags).
// ---------------------------------------------------------------------------
__global__ void params_kernel(const float* __restrict__ x) {
    const int b = blockIdx.x;
    const int lane = threadIdx.x;
    const unsigned FULL = 0xFFFFFFFFu;

    // root key(42) = (0,42); split -> kflip=tf(key,(0,0)), kparams=tf(key,(0,1))
    uint32_t kf0, kf1, kp0, kp1;
    tf2x32(0u, 42u, 0u, 0u, kf0, kf1);
    tf2x32(0u, 42u, 0u, 1u, kp0, kp1);

    const int img_stride = 3 * HM * WMETA;
    float Hf = __ldg(x + b * img_stride + 512);
    float Wf = __ldg(x + b * img_stride + HM * WMETA + 512);

    const float lg_lo = -0.22314355131420976f;  // float32(log(0.8))
    const float lg_hi =  0.22314355131420976f;  // float32(log(1.25))

    int   flip = 0;
    bool  valid = false;
    float ch = 0.f, cw = 0.f, ri = 0.f, rj = 0.f;

    if (lane < 10) {
        uint32_t kt0, kt1;
        tf2x32(kp0, kp1, 0u, (uint32_t)lane, kt0, kt1);
        uint32_t ka0, ka1, kb0, kb1, kc0, kc1, kd0, kd1;
        tf2x32(kt0, kt1, 0u, 0u, ka0, ka1);  // target_area
        tf2x32(kt0, kt1, 0u, 1u, kb0, kb1);  // aspect
        tf2x32(kt0, kt1, 0u, 2u, kc0, kc1);  // rand_i
        tf2x32(kt0, kt1, 0u, 3u, kd0, kd1);  // rand_j

        float u1 = bits_to_unit(rbits_part(ka0, ka1, b));
        u1 = fmaxf(0.1f, __fadd_rn(__fmul_rn(u1, 1.0f - 0.1f), 0.1f));
        float u2 = bits_to_unit(rbits_part(kb0, kb1, b));
        u2 = fmaxf(lg_lo, __fadd_rn(__fmul_rn(u2, lg_hi - lg_lo), lg_lo));

        float area = __fmul_rn(Hf, Wf);
        float ta = __fmul_rn(area, u1);
        float aspect = expf(u2);   // libdevice __nv_expf
        cw = rintf(__fsqrt_rn(__fmul_rn(ta, aspect)));
        ch = rintf(__fsqrt_rn(__fdiv_rn(ta, aspect)));

        valid = (cw > 0.0f) && (cw <= Wf) && (ch > 0.0f) && (ch <= Hf);

        float max_i = fmaxf(__fadd_rn(__fsub_rn(Hf, ch), 1.0f), 1.0f);
        float max_j = fmaxf(__fadd_rn(__fsub_rn(Wf, cw), 1.0f), 1.0f);
        float u3 = bits_to_unit(rbits_part(kc0, kc1, b));
        float u4 = bits_to_unit(rbits_part(kd0, kd1, b));
        ri = floorf(__fmul_rn(u3, max_i));
        rj = floorf(__fmul_rn(u4, max_j));
    } else if (lane == 10) {
        flip = bits_to_unit(rbits_part(kf0, kf1, b)) > 0.5f;
    }

    unsigned vmask = __ballot_sync(FULL, valid) & 0x3FFu;
    int src = vmask ? (__ffs(vmask) - 1) : -1;

    float fh, fw, fi, fj;
    if (src >= 0) {
        fh = __shfl_sync(FULL, ch, src);
        fw = __shfl_sync(FULL, cw, src);
        fi = __shfl_sync(FULL, ri, src);
        fj = __shfl_sync(FULL, rj, src);
    } else {
        float in_ratio = __fdiv_rn(Wf, Hf);
        fw = (in_ratio > 1.25f) ? rintf(__fmul_rn(Hf, 1.25f)) : Wf;
        fh = (in_ratio < 0.8f)  ? rintf(__fdiv_rn(Wf, 0.8f))  : Hf;
        fi = floorf(__fdiv_rn(__fsub_rn(Hf, fh), 2.0f));
        fj = floorf(__fdiv_rn(__fsub_rn(Wf, fw), 2.0f));
    }
    int flipv = __shfl_sync(FULL, flip, 10);

    if (lane == 0) {
        int4 p;
        p.x = (int)fi;
        p.y = (int)fj;
        p.z = (int)fh;
        p.w = (int)fw | (flipv << 16);
        g_prm[b] = p;
    }
}

// ---------------------------------------------------------------------------
// Kernel 2: flip + crop + bilinear resize (direct gather, 32-bit indexing).
// One block per (b, 4-row group); 224 threads. Each thread: 1 ox, 4 oy rows,
// 3 channels = 48 front-batched gathers (x-mapping shared across rows).
// ---------------------------------------------------------------------------
__global__ void __launch_bounds__(OSIZE)
resize_kernel(const float* __restrict__ x, float* __restrict__ out) {
    const int ox  = threadIdx.x;               // 0..223
    const int oy0 = blockIdx.x * ROWS_PER_BLK; // 0,4,..,220
    const int b   = blockIdx.y;                // 0..63

    const int4 p = __ldg(&g_prm[b]);
    const int ci = p.x, cj = p.y, ch = p.z;
    const int cw = p.w & 0xFFFF;
    const int flip = p.w >> 16;
    const float hf = (float)ch, wf = (float)cw;

    // x mapping (shared by all rows), IEEE ops so floors match XLA
    float xsv = __fsub_rn(__fdiv_rn(__fmul_rn((float)ox + 0.5f, wf), 224.0f), 0.5f);
    xsv = fminf(fmaxf(xsv, 0.0f), wf - 1.0f);
    float x0f = floorf(xsv);
    float wx = xsv - x0f;
    int x0 = min(max((int)x0f + cj, 0), WMC - 1);
    int xtop = min(max(cj + cw - 1, 0), WMC - 1);
    int x1 = min(max(x0 + 1, 0), xtop);
    if (flip) { x0 = WMC - x0; x1 = WMC - x1; }

    // y mappings for the rows
    const int ytop = min(max(ci + ch - 1, 0), HM - 1);
    int y0r[ROWS_PER_BLK], y1r[ROWS_PER_BLK];
    float wyr[ROWS_PER_BLK];
#pragma unroll
    for (int r = 0; r < ROWS_PER_BLK; r++) {
        float ysv = __fsub_rn(__fdiv_rn(__fmul_rn((float)(oy0 + r) + 0.5f, hf), 224.0f), 0.5f);
        ysv = fminf(fmaxf(ysv, 0.0f), hf - 1.0f);
        float y0f = floorf(ysv);
        wyr[r] = ysv - y0f;
        int y0 = min(max((int)y0f + ci, 0), HM - 1);
        y0r[r] = y0;
        y1r[r] = min(max(y0 + 1, 0), ytop);
    }

    const int base = b * (3 * HM * WMETA);

    // Front-batched gathers: 4 rows x 3 channels x 4 taps = 48 independent LDGs
    float g00[ROWS_PER_BLK][3], g01[ROWS_PER_BLK][3];
    float g10[ROWS_PER_BLK][3], g11[ROWS_PER_BLK][3];
#pragma unroll
    for (int r = 0; r < ROWS_PER_BLK; r++) {
        const int r0 = base + y0r[r] * WMETA;
        const int r1 = base + y1r[r] * WMETA;
#pragma unroll
        for (int c = 0; c < 3; c++) {
            const int co = c * (HM * WMETA);
            g00[r][c] = __ldg(x + r0 + co + x0);
            g01[r][c] = __ldg(x + r0 + co + x1);
            g10[r][c] = __ldg(x + r1 + co + x0);
            g11[r][c] = __ldg(x + r1 + co + x1);
        }
    }

    const float omwx = 1.0f - wx;
    const int obase = (b * 3 * OSIZE + oy0) * OSIZE + ox;  // row stride OSIZE

#pragma unroll
    for (int r = 0; r < ROWS_PER_BLK; r++) {
        const float wy = wyr[r], omwy = 1.0f - wy;
#pragma unroll
        for (int c = 0; c < 3; c++) {
            float top = omwx * g00[r][c] + wx * g01[r][c];
            float bot = omwx * g10[r][c] + wx * g11[r][c];
            out[obase + c * (OSIZE * OSIZE) + r * OSIZE] = omwy * top + wy * bot;
        }
    }
}

extern "C" void kernel_launch(void* const* d_in, const int* in_sizes, int n_in,
                              void* d_out, int out_size) {
    const float* x = (const float*)d_in[0];
    float* out = (float*)d_out;

    params_kernel<<<NB, 32>>>(x);
    dim3 grid(OSIZE / ROWS_PER_BLK, NB);
    resize_kernel<<<grid, OSIZE>>>(x, out);
}